// round 16
// baseline (speedup 1.0000x reference)
#include <cuda_runtime.h>
#include <cuda_fp16.h>
#include <stdint.h>
#include <math.h>

#define SEQ   2048
#define NXC   768
#define NH    12
#define HD    64
#define BSZ   2
#define MROWS 4096
#define QKVN  (3*NXC)        // 2304

#define LOG2E  1.4426950408889634f
#define MASKEDL (-10000.0f * LOG2E)

// Scratch (static __device__ — no allocations allowed). All fp16.
__device__ __align__(16) __half g_qkv[3ull * MROWS * NXC];
__device__ __align__(16) __half g_att[(size_t)MROWS * NXC];
__device__ __align__(16) __half g_x [(size_t)MROWS * NXC];
__device__ __align__(16) __half g_wa[(size_t)NXC * QKVN];
__device__ __align__(16) __half g_wp[(size_t)NXC * NXC];
// Split-KV partials for qb>=10
__device__ __align__(16) float g_pO[2][BSZ*NH*6][128*64];
__device__ float g_pM[2][BSZ*NH*6][128];
__device__ float g_pL[2][BSZ*NH*6][128];
__device__ int   g_flag[BSZ*NH*6];   // zero-init; merger resets to 0

__device__ const signed char ITEM_QB[22] =
    {9,8,15,15,7,14,14,13,13,6,12,12,5,11,11,10,10,4,3,2,1,0};
__device__ const signed char ITEM_PC[22] =
    {-1,-1,0,1,-1,0,1,0,1,-1,0,1,-1,0,1,0,1,-1,-1,-1,-1,-1};

__device__ __forceinline__ unsigned h2u(float lo, float hi) {
    __half2 h = __floats2half2_rn(lo, hi);
    return *reinterpret_cast<unsigned*>(&h);
}

__device__ __forceinline__ void mma_f16(float* d,
    unsigned a0, unsigned a1, unsigned a2, unsigned a3,
    unsigned b0, unsigned b1)
{
    asm volatile(
        "mma.sync.aligned.m16n8k16.row.col.f32.f16.f16.f32 "
        "{%0,%1,%2,%3},{%4,%5,%6,%7},{%8,%9},{%0,%1,%2,%3};"
        : "+f"(d[0]), "+f"(d[1]), "+f"(d[2]), "+f"(d[3])
        : "r"(a0), "r"(a1), "r"(a2), "r"(a3), "r"(b0), "r"(b1));
}

__device__ __forceinline__ void ldmx4(unsigned& r0, unsigned& r1,
                                      unsigned& r2, unsigned& r3, unsigned addr) {
    asm volatile("ldmatrix.sync.aligned.m8n8.x4.shared.b16 {%0,%1,%2,%3}, [%4];"
                 : "=r"(r0), "=r"(r1), "=r"(r2), "=r"(r3) : "r"(addr));
}
__device__ __forceinline__ void ldmx4t(unsigned& r0, unsigned& r1,
                                       unsigned& r2, unsigned& r3, unsigned addr) {
    asm volatile("ldmatrix.sync.aligned.m8n8.x4.trans.shared.b16 {%0,%1,%2,%3}, [%4];"
                 : "=r"(r0), "=r"(r1), "=r"(r2), "=r"(r3) : "r"(addr));
}

__device__ __forceinline__ unsigned ex2_h2(unsigned x) {
    unsigned r; asm("ex2.approx.f16x2 %0, %1;" : "=r"(r) : "r"(x)); return r;
}
__device__ __forceinline__ float ex2_f(float x) {
    float r; asm("ex2.approx.f32 %0, %1;" : "=f"(r) : "f"(x)); return r;
}
__device__ __forceinline__ void cp16(unsigned dst, const void* src) {
    asm volatile("cp.async.cg.shared.global [%0], [%1], 16;"
                 :: "r"(dst), "l"(src));
}
#define CP_COMMIT()  asm volatile("cp.async.commit_group;")
#define CP_WAIT(n)   asm volatile("cp.async.wait_group " #n ";")
__device__ __forceinline__ unsigned smem_u32(const void* p) {
    return (unsigned)__cvta_generic_to_shared(p);
}

// ---------------------------------------------------------------------------
// Fused pack kernel (frozen from round 15)
// ---------------------------------------------------------------------------
__device__ __forceinline__ void packA_body(const float* __restrict__ src,
                                           __half* __restrict__ dst,
                                           int idx, int M, int K)
{
    int lane = idx & 31;
    int mg   = (idx >> 5) & ((M / 16) - 1);
    int kb   = idx / (32 * (M / 16));
    if (kb >= K / 16) return;
    int lq = lane >> 2, lr = lane & 3;
    const float* s = src + (size_t)(mg * 16 + lq) * K + kb * 16 + 2 * lr;
    uint4 v;
    v.x = h2u(s[0],         s[1]);
    v.y = h2u(s[8 * K],     s[8 * K + 1]);
    v.z = h2u(s[8],         s[9]);
    v.w = h2u(s[8 * K + 8], s[8 * K + 9]);
    *(uint4*)(dst + (size_t)idx * 8) = v;
}

__device__ __forceinline__ void packB_body(const float* __restrict__ src,
                                           __half* __restrict__ dst,
                                           int idx, int K, int N)
{
    int lane = idx & 31;
    int ng   = (idx >> 5) % (N / 8);
    int kb   = idx / (32 * (N / 8));
    if (kb >= K / 16) return;
    int lq = lane >> 2, lr = lane & 3;
    const float* s = src + (size_t)(kb * 16 + 2 * lr) * N + ng * 8 + lq;
    uint2 v;
    v.x = h2u(s[0],     s[N]);
    v.y = h2u(s[8 * N], s[9 * N]);
    *(uint2*)(dst + (size_t)idx * 4) = v;
}

#define PACKA_BLKS 1536
#define PACKWA_BLKS 1728
#define PACKWP_BLKS 576

__global__ void pack_all_kernel(const float* __restrict__ x,
                                const float* __restrict__ wa,
                                const float* __restrict__ wp,
                                __half* __restrict__ gx,
                                __half* __restrict__ gwa,
                                __half* __restrict__ gwp)
{
    int bid = blockIdx.x;
    if (bid < PACKA_BLKS) {
        packA_body(x, gx, bid * 256 + threadIdx.x, MROWS, NXC);
    } else if (bid < PACKA_BLKS + PACKWA_BLKS) {
        packB_body(wa, gwa, (bid - PACKA_BLKS) * 256 + threadIdx.x, NXC, QKVN);
    } else {
        packB_body(wp, gwp, (bid - PACKA_BLKS - PACKWA_BLKS) * 256 + threadIdx.x,
                   NXC, NXC);
    }
}

// ---------------------------------------------------------------------------
// fp16 GEMM on fragment-packed operands (frozen). BK=64, 3-stage cp.async.
// ---------------------------------------------------------------------------
#define GSTG_H 8192
#define GSMEM_DYN (6 * GSTG_H * 2)   // 98304 B

template<int SPLITOUT>
__global__ void __launch_bounds__(256, 2)
gemm_tc(const __half* __restrict__ A, const __half* __restrict__ B,
        const float* __restrict__ bias, float* __restrict__ C,
        int M, int N, int K)
{
    extern __shared__ __half sg[];
    __half* As = sg;
    __half* Bs = sg + 3 * GSTG_H;

    int tid  = threadIdx.x;
    int lane = tid & 31;
    int w    = tid >> 5;
    int wm   = w & 1;
    int wn   = w >> 1;
    int lq   = lane >> 2;
    int lr   = lane & 3;

    int brow16 = blockIdx.y * 8;
    int bcol8  = blockIdx.x * 16;
    const int M16 = M / 16, N8 = N / 8;

    float acc[4][4][4];
    #pragma unroll
    for (int mi = 0; mi < 4; mi++)
        #pragma unroll
        for (int ni = 0; ni < 4; ni++)
            #pragma unroll
            for (int j = 0; j < 4; j++) acc[mi][ni][j] = 0.f;

    const int NT = K / 64;

    auto issue = [&](int t, int s) {
        __half* as = As + s * GSTG_H;
        __half* bs = Bs + s * GSTG_H;
        #pragma unroll
        for (int j = 0; j < 4; j++) {
            const __half* gA = A + ((size_t)(4 * t + j) * M16 + brow16) * 256 + tid * 8;
            cp16(smem_u32(as + j * 2048 + tid * 8), gA);
            const __half* gB = B + ((size_t)(4 * t + j) * N8 + bcol8) * 128 + tid * 8;
            cp16(smem_u32(bs + j * 2048 + tid * 8), gB);
        }
        CP_COMMIT();
    };

    issue(0, 0);
    issue(1, 1);

    for (int t = 0; t < NT; t++) {
        CP_WAIT(1);
        __syncthreads();
        if (t + 2 < NT) issue(t + 2, (t + 2) % 3);

        const __half* as0 = As + (t % 3) * GSTG_H + wm * 1024 + lane * 8;
        const __half* bs0 = Bs + (t % 3) * GSTG_H + wn * 512 + lane * 4;
        #pragma unroll
        for (int kk = 0; kk < 4; kk++) {
            const __half* as = as0 + kk * 2048;
            const __half* bs = bs0 + kk * 2048;
            uint4 af[4];
            #pragma unroll
            for (int mi = 0; mi < 4; mi++)
                af[mi] = *(const uint4*)(as + mi * 256);
            #pragma unroll
            for (int ni = 0; ni < 4; ni++) {
                uint2 bf = *(const uint2*)(bs + ni * 128);
                #pragma unroll
                for (int mi = 0; mi < 4; mi++)
                    mma_f16(acc[mi][ni], af[mi].x, af[mi].y, af[mi].z, af[mi].w,
                            bf.x, bf.y);
            }
        }
    }

    #pragma unroll
    for (int mi = 0; mi < 4; mi++) {
        int r0 = brow16 * 16 + wm * 64 + mi * 16 + lq;
        #pragma unroll
        for (int ni = 0; ni < 4; ni++) {
            int col = bcol8 * 8 + wn * 32 + ni * 8 + lr * 2;
            float bv0 = bias[col], bv1 = bias[col + 1];
            float v00 = acc[mi][ni][0] + bv0, v01 = acc[mi][ni][1] + bv1;
            float v10 = acc[mi][ni][2] + bv0, v11 = acc[mi][ni][3] + bv1;
            if (SPLITOUT == 0) {
                *(float2*)(C + (size_t)r0 * N + col) = make_float2(v00, v01);
                *(float2*)(C + (size_t)(r0 + 8) * N + col) = make_float2(v10, v11);
            } else {
                int part = col / NXC;
                int c = col - part * NXC;
                float sc = (part == 0) ? (0.125f * LOG2E) : 1.0f;
                __half* dst = g_qkv + (size_t)part * MROWS * NXC + c;
                *(unsigned*)(dst + (size_t)r0 * NXC) = h2u(v00 * sc, v01 * sc);
                *(unsigned*)(dst + (size_t)(r0 + 8) * NXC) = h2u(v10 * sc, v11 * sc);
            }
        }
    }
}

// ---------------------------------------------------------------------------
// Flash attention with split-KV balancing + INLINE split-K merge.
// The second-arriving piece of each split item merges partials into g_att
// (same fp32 math as the old combine kernel -> bit-identical output).
// ---------------------------------------------------------------------------
__global__ void __launch_bounds__(256, 2) attn_kernel(const float* __restrict__ amask)
{
    __shared__ __half kvs[2][2][4096];
    __shared__ int s_old;

    int h  = blockIdx.x;
    int b  = blockIdx.y;
    int item = blockIdx.z;
    int qb = ITEM_QB[item];
    int pc = ITEM_PC[item];
    int tid  = threadIdx.x;
    int lane = tid & 31;
    int w    = tid >> 5;
    int lq   = lane >> 2;
    int lr   = lane & 3;

    const size_t bh = (size_t)b * SEQ * NXC + (size_t)h * SEQ * HD;
    const __half* Qg = g_qkv + bh;
    const __half* Kg = g_qkv + (size_t)MROWS * NXC + bh;
    const __half* Vg = g_qkv + 2ull * MROWS * NXC + bh;
    const float* am = amask + (size_t)b * SEQ;

    int kb0, kbN;
    if (pc < 0)      { kb0 = 0;      kbN = 2 * qb + 2; }
    else if (pc == 0){ kb0 = 0;      kbN = qb + 1; }
    else             { kb0 = qb + 1; kbN = 2 * qb + 2; }

    int qrow = qb * 128 + w * 16 + lq;
    const __half* qr  = Qg + (size_t)qrow * HD;
    const __half* qr8 = Qg + (size_t)(qrow + 8) * HD;
    unsigned qa[4][4];
    #pragma unroll
    for (int ks = 0; ks < 4; ks++) {
        qa[ks][0] = *(const unsigned*)(qr  + ks * 16 + 2 * lr);
        qa[ks][1] = *(const unsigned*)(qr8 + ks * 16 + 2 * lr);
        qa[ks][2] = *(const unsigned*)(qr  + ks * 16 + 2 * lr + 8);
        qa[ks][3] = *(const unsigned*)(qr8 + ks * 16 + 2 * lr + 8);
    }

    float o[8][4];
    #pragma unroll
    for (int dj = 0; dj < 8; dj++)
        #pragma unroll
        for (int j = 0; j < 4; j++) o[dj][j] = 0.f;
    float m0 = -INFINITY, m1 = -INFINITY, l0 = 0.f, l1 = 0.f;

    auto issue = [&](int kb) {
        __half* kd = kvs[kb & 1][0];
        __half* vd = kvs[kb & 1][1];
        const __half* kg = Kg + (size_t)kb * 64 * HD;
        const __half* vg = Vg + (size_t)kb * 64 * HD;
        #pragma unroll
        for (int i = 0; i < 2; i++) {
            int f = tid + i * 256;
            int r = f >> 3, c = f & 7;
            int sw = r * 64 + ((c ^ (r & 7)) << 3);
            cp16(smem_u32(kd + sw), kg + r * 64 + c * 8);
            cp16(smem_u32(vd + sw), vg + r * 64 + c * 8);
        }
        CP_COMMIT();
    };

    issue(kb0);

    for (int kb = kb0; kb < kbN; kb++) {
        CP_WAIT(0);
        __syncthreads();
        if (kb + 1 < kbN) issue(kb + 1);

        const __half* Ks = kvs[kb & 1][0];
        const __half* Vs = kvs[kb & 1][1];

        // ---- S = Q @ K^T : K b-frags via ldmatrix.x4 ----
        float s[8][4];
        #pragma unroll
        for (int ni = 0; ni < 8; ni++)
            #pragma unroll
            for (int j = 0; j < 4; j++) s[ni][j] = 0.f;

        {
            int keyrow = lane & 7;
            int cgrp   = lane >> 3;
            #pragma unroll
            for (int ni = 0; ni < 8; ni++) {
                int key = ni * 8 + keyrow;
                const __half* kr = Ks + key * 64;
                unsigned kf[8];
                ldmx4(kf[0], kf[1], kf[2], kf[3],
                      smem_u32(kr + ((cgrp ^ (key & 7)) << 3)));
                ldmx4(kf[4], kf[5], kf[6], kf[7],
                      smem_u32(kr + (((cgrp + 4) ^ (key & 7)) << 3)));
                #pragma unroll
                for (int ks = 0; ks < 4; ks++)
                    mma_f16(s[ni], qa[ks][0], qa[ks][1], qa[ks][2], qa[ks][3],
                            kf[2 * ks], kf[2 * ks + 1]);
            }
        }

        // ---- mask + attention_mask*log2e + row max (split paths) ----
        float rm0 = -INFINITY, rm1 = -INFINITY;
        if (kb >= 2 * qb) {
            #pragma unroll
            for (int ni = 0; ni < 8; ni++) {
                int gc0 = kb * 64 + ni * 8 + 2 * lr;
                float2 amv = *(const float2*)(am + gc0);
                float b00 = s[ni][0], b01 = s[ni][1];
                float b10 = s[ni][2], b11 = s[ni][3];
                if (gc0     > qrow)     b00 = MASKEDL;
                if (gc0 + 1 > qrow)     b01 = MASKEDL;
                if (gc0     > qrow + 8) b10 = MASKEDL;
                if (gc0 + 1 > qrow + 8) b11 = MASKEDL;
                float v00 = fmaf(amv.x, LOG2E, b00);
                float v01 = fmaf(amv.y, LOG2E, b01);
                float v10 = fmaf(amv.x, LOG2E, b10);
                float v11 = fmaf(amv.y, LOG2E, b11);
                s[ni][0] = v00; s[ni][1] = v01; s[ni][2] = v10; s[ni][3] = v11;
                rm0 = fmaxf(rm0, fmaxf(v00, v01));
                rm1 = fmaxf(rm1, fmaxf(v10, v11));
            }
        } else {
            #pragma unroll
            for (int ni = 0; ni < 8; ni++) {
                int gc0 = kb * 64 + ni * 8 + 2 * lr;
                float2 amv = *(const float2*)(am + gc0);
                float v00 = fmaf(amv.x, LOG2E, s[ni][0]);
                float v01 = fmaf(amv.y, LOG2E, s[ni][1]);
                float v10 = fmaf(amv.x, LOG2E, s[ni][2]);
                float v11 = fmaf(amv.y, LOG2E, s[ni][3]);
                s[ni][0] = v00; s[ni][1] = v01; s[ni][2] = v10; s[ni][3] = v11;
                rm0 = fmaxf(rm0, fmaxf(v00, v01));
                rm1 = fmaxf(rm1, fmaxf(v10, v11));
            }
        }
        #pragma unroll
        for (int off = 1; off <= 2; off <<= 1) {
            rm0 = fmaxf(rm0, __shfl_xor_sync(0xffffffffu, rm0, off));
            rm1 = fmaxf(rm1, __shfl_xor_sync(0xffffffffu, rm1, off));
        }

        // ---- online softmax ----
        float mn0 = fmaxf(m0, rm0), mn1 = fmaxf(m1, rm1);
        float al0 = ex2_f(m0 - mn0), al1 = ex2_f(m1 - mn1);
        unsigned plo[8], phi[8];
        #pragma unroll
        for (int ni = 0; ni < 8; ni++) {
            plo[ni] = ex2_h2(h2u(s[ni][0] - mn0, s[ni][1] - mn0));
            phi[ni] = ex2_h2(h2u(s[ni][2] - mn1, s[ni][3] - mn1));
        }

        float ls[4] = {0.f, 0.f, 0.f, 0.f};
        #pragma unroll
        for (int t = 0; t < 4; t++)
            mma_f16(ls, plo[2*t], phi[2*t], plo[2*t+1], phi[2*t+1],
                    0x3C003C00u, 0x3C003C00u);
        l0 = l0 * al0 + ls[0];
        l1 = l1 * al1 + ls[2];
        m0 = mn0; m1 = mn1;

        #pragma unroll
        for (int dj = 0; dj < 8; dj++) {
            o[dj][0] *= al0; o[dj][1] *= al0;
            o[dj][2] *= al1; o[dj][3] *= al1;
        }

        // ---- O += P @ V ----
        #pragma unroll
        for (int t = 0; t < 4; t++) {
            int row = 16 * t + (lane & 15);
            int cadd = lane >> 4;
            #pragma unroll
            for (int dj = 0; dj < 8; dj += 2) {
                int c = dj + cadd;
                unsigned b0, b1, b2, b3;
                ldmx4t(b0, b1, b2, b3,
                       smem_u32(Vs + row * 64 + ((c ^ (row & 7)) << 3)));
                mma_f16(o[dj],     plo[2*t], phi[2*t], plo[2*t+1], phi[2*t+1], b0, b1);
                mma_f16(o[dj + 1], plo[2*t], phi[2*t], plo[2*t+1], phi[2*t+1], b2, b3);
            }
        }
    }

    if (pc < 0) {
        // Full item: normalize, write g_att frag-packed.
        float inv0 = 1.0f / l0, inv1 = 1.0f / l1;
        int mg = b * (SEQ / 16) + qb * 8 + w;
        #pragma unroll
        for (int dj = 0; dj < 8; dj++) {
            int kg16 = h * 4 + (dj >> 1);
            __half* p = g_att + ((size_t)(kg16 * (MROWS / 16) + mg) * 32 + lane) * 8
                              + (dj & 1) * 4;
            *(unsigned*)(p)     = h2u(o[dj][0] * inv0, o[dj][1] * inv0);
            *(unsigned*)(p + 2) = h2u(o[dj][2] * inv1, o[dj][3] * inv1);
        }
        return;
    }

    // Split piece: write unnormalized partials.
    int it = (b * NH + h) * 6 + (qb - 10);
    {
        int prow = w * 16 + lq;
        #pragma unroll
        for (int dj = 0; dj < 8; dj++) {
            int col0 = dj * 8 + 2 * lr;
            *(float2*)&g_pO[pc][it][prow * 64 + col0] =
                make_float2(o[dj][0], o[dj][1]);
            *(float2*)&g_pO[pc][it][(prow + 8) * 64 + col0] =
                make_float2(o[dj][2], o[dj][3]);
        }
        if (lr == 0) {
            g_pM[pc][it][prow]     = m0;
            g_pM[pc][it][prow + 8] = m1;
            g_pL[pc][it][prow]     = l0;
            g_pL[pc][it][prow + 8] = l1;
        }
    }

    // Inline split-K merge: second-arriving block merges (output symmetric
    // in the two pieces -> deterministic result regardless of winner).
    __threadfence();
    __syncthreads();
    if (tid == 0) s_old = atomicAdd(&g_flag[it], 1);
    __syncthreads();
    if (s_old == 1) {
        __threadfence();   // acquire: other piece's partials now visible
        int row = tid >> 1;
        int c0  = (tid & 1) * 32;

        float mA = g_pM[0][it][row], mB = g_pM[1][it][row];
        float lA = g_pL[0][it][row], lB = g_pL[1][it][row];
        float ms = fmaxf(mA, mB);
        float a1 = ex2_f(mA - ms), a2 = ex2_f(mB - ms);
        float inv = 1.0f / (lA * a1 + lB * a2);
        float s1 = a1 * inv, s2 = a2 * inv;

        int grow = b * SEQ + qb * 128 + row;
        int mg = grow >> 4;
        int rq = grow & 15;
        int lqf = rq & 7, rowhi = rq >> 3;

        const float* O1 = &g_pO[0][it][row * 64 + c0];
        const float* O2 = &g_pO[1][it][row * 64 + c0];

        #pragma unroll
        for (int j = 0; j < 32; j += 2) {
            float2 v1 = *(const float2*)(O1 + j);
            float2 v2 = *(const float2*)(O2 + j);
            float val0 = v1.x * s1 + v2.x * s2;
            float val1 = v1.y * s1 + v2.y * s2;
            int cg = h * 64 + c0 + j;
            int kb16 = cg >> 4;
            int cq = cg & 15;
            int lrf = (cq & 7) >> 1, chi = cq >> 3;
            __half* p = g_att + ((size_t)(kb16 * (MROWS / 16) + mg) * 32
                                 + lqf * 4 + lrf) * 8 + chi * 4 + rowhi * 2;
            *(unsigned*)p = h2u(val0, val1);
        }
        __syncthreads();
        if (tid == 0) g_flag[it] = 0;   // reset for next graph replay
    }
}

extern "C" void kernel_launch(void* const* d_in, const int* in_sizes, int n_in,
                              void* d_out, int out_size)
{
    const float* x      = (const float*)d_in[0];
    const float* amask  = (const float*)d_in[1];
    const float* w_attn = (const float*)d_in[2];
    const float* b_attn = (const float*)d_in[3];
    const float* w_proj = (const float*)d_in[4];
    const float* b_proj = (const float*)d_in[5];
    float* out = (float*)d_out;

    // Device addresses of __device__ symbols (round-4 lesson).
    __half *gx, *gwa, *gwp, *gatt;
    cudaGetSymbolAddress((void**)&gx,   g_x);
    cudaGetSymbolAddress((void**)&gwa,  g_wa);
    cudaGetSymbolAddress((void**)&gwp,  g_wp);
    cudaGetSymbolAddress((void**)&gatt, g_att);

    // 0) fused pack: all three inputs in one launch
    pack_all_kernel<<<PACKA_BLKS + PACKWA_BLKS + PACKWP_BLKS, 256>>>(
        x, w_attn, w_proj, gx, gwa, gwp);

    cudaFuncSetAttribute(gemm_tc<1>,
                         cudaFuncAttributeMaxDynamicSharedMemorySize, GSMEM_DYN);
    cudaFuncSetAttribute(gemm_tc<0>,
                         cudaFuncAttributeMaxDynamicSharedMemorySize, GSMEM_DYN);

    // 1) QKV projection -> g_qkv halves (Q pre-scaled by 0.125*log2e)
    gemm_tc<1><<<dim3(QKVN / 128, MROWS / 128), 256, GSMEM_DYN>>>(
        gx, gwa, b_attn, nullptr, MROWS, QKVN, NXC);

    // 2) Flash attention, split-KV balanced, inline merge
    attn_kernel<<<dim3(NH, BSZ, 22), 256>>>(amask);

    // 3) Output projection -> d_out (fp32)
    gemm_tc<0><<<dim3(NXC / 128, MROWS / 128), 256, GSMEM_DYN>>>(
        gatt, gwp, b_proj, out, MROWS, NXC, NXC);
}